// round 16
// baseline (speedup 1.0000x reference)
#include <cuda_runtime.h>
#include <cuda_bf16.h>
#include <math.h>

#define BATCH   32
#define DIM     4096
#define NKV     8
#define REP     4
#define HD      128
#define QKVN    6144      // (32 + 2*8) * 128
#define CL      2176      // cache length
#define NCH     17        // 17 * 128 = 2176
#define KSPLIT_QKV  32
#define KSPLIT_WO   64
#define WCH     8         // weight-chunk rows (8 x 256 cols = 8 KB per buffer)

// ---------------- f32x2 packed-math helpers -----------------------------------
#define FFMA2(d, a, b, c) \
    asm("fma.rn.f32x2 %0, %1, %2, %3;" : "=l"(d) : "l"(a), "l"(b), "l"(c))
#define PACK2(d, s) \
    asm("mov.b64 %0, {%1, %1};" : "=l"(d) : "f"(s))
#define UNPACK2(lo, hi, v) \
    asm("mov.b64 {%0, %1}, %2;" : "=f"(lo), "=f"(hi) : "l"(v))
#define LDSV2(p01, p23, addr) \
    asm("ld.shared.v2.u64 {%0, %1}, [%2];" : "=l"(p01), "=l"(p23) : "r"(addr))

// vectorized no-return reduction (sm_90+): adds {a,b} to 8B-aligned global pair
#define REDG2(ptr, a, b) \
    asm volatile("red.global.add.v2.f32 [%0], {%1, %2};" \
                 :: "l"(ptr), "f"(a), "f"(b) : "memory")

// ---------------- cp.async helpers ---------------------------------------------
#define CP_ASYNC16(dst_s, src_g) \
    asm volatile("cp.async.cg.shared.global [%0], [%1], 16;" \
                 :: "r"(dst_s), "l"(src_g) : "memory")
#define CP_COMMIT() asm volatile("cp.async.commit_group;" ::: "memory")
#define CP_WAIT(n)  asm volatile("cp.async.wait_group %0;" :: "n"(n) : "memory")

// ---------------- scratch (static device globals; no allocs allowed) ----------
__device__ float g_qkv[BATCH * QKVN];                    // 0.79 MB (L2-resident)
__device__ float g_q[BATCH * DIM];                       // (b, g, r, d)
__device__ float g_k[BATCH * NKV * HD];
__device__ float g_v[BATCH * NKV * HD];
__device__ float g_pacc[(size_t)BATCH * NKV * NCH * REP * HD];
__device__ float g_pm[BATCH * NKV * NCH * REP];
__device__ float g_pl[BATCH * NKV * NCH * REP];
__device__ float g_attn[BATCH * DIM];

// ---------------- skinny GEMM v6: 8-row weight chunks (higher occupancy) -------
// out[32, N] accumulated over K-splits via red.global.add.v2.f32 into a compact
// L2-resident destination (g_qkv for QKV; d_out for WO). grid(N/256, NSPLIT),
// 128 threads; thread owns adjacent cols (nblk+2t, nblk+2t+1).
// Weight chunks: 8 rows x 256 cols (8 KB), double-buffered -> smem/block drops
// to 34.8 KB (QKV, 6 blocks/SM) / 25.6 KB (WO, 8 blocks/SM).
// Final chunk uses wait_group 0 (R8 race fix). Same per-thread k-order as v5
// (bitwise-identical numerics).
template<int N, bool WO, int KC>
__global__ __launch_bounds__(128) void k_gemm6(const float* __restrict__ xsrc,
                                               const float* __restrict__ w,
                                               float* __restrict__ dstout) {
    extern __shared__ float smg[];
    float* xs_t = smg;                 // KC * 36 floats
    float* wt   = smg + KC * 36;       // 2 * WCH * 256 floats

    const int t    = threadIdx.x;
    const int k0   = blockIdx.y * KC;
    const int nblk = blockIdx.x * 256;
    constexpr int NCHW = KC / WCH;     // weight chunks

    const unsigned wts = (unsigned)__cvta_generic_to_shared(wt);

    // issue weight chunk cb (WCH rows x 256 cols = 8 KB) into buffer cb&1
    auto issue = [&](int cb) {
        const float* src = w + (size_t)(k0 + cb * WCH) * N + nblk;
        unsigned dsts = wts + (cb & 1) * (WCH * 256 * 4);
        #pragma unroll
        for (int it = 0; it < WCH * 64 / 128; it++) {
            int idx = t + 128 * it;            // 0 .. WCH*64-1
            int row = idx >> 6;                // 64 x 16B per row
            int c16 = idx & 63;
            CP_ASYNC16(dsts + (row * 256 + c16 * 4) * 4,
                       (const void*)(src + (size_t)row * N + c16 * 4));
        }
        CP_COMMIT();
    };
    issue(0);
    issue(1);

    if (WO) cudaGridDependencySynchronize();   // g_attn + zeroed d_out ready

    const float* xbase = WO ? (const float*)g_attn : xsrc;
    float*       dst   = WO ? dstout : (float*)g_qkv;

    // load + transpose x chunk: [32][KC] -> xs_t[k][m]
    const float4* xg = (const float4*)xbase;
    #pragma unroll
    for (int j = t; j < 8 * KC; j += 128) {
        int m  = j / (KC / 4);
        int c4 = j % (KC / 4);
        float4 v = xg[m * (DIM / 4) + (k0 >> 2) + c4];
        xs_t[(4 * c4 + 0) * 36 + m] = v.x;
        xs_t[(4 * c4 + 1) * 36 + m] = v.y;
        xs_t[(4 * c4 + 2) * 36 + m] = v.z;
        xs_t[(4 * c4 + 3) * 36 + m] = v.w;
    }

    const unsigned xa = (unsigned)__cvta_generic_to_shared(xs_t);

    unsigned long long acc0[16], acc1[16];
    #pragma unroll
    for (int mp = 0; mp < 16; mp++) { acc0[mp] = 0ull; acc1[mp] = 0ull; }

    for (int cb = 0; cb < NCHW; cb++) {
        if (cb + 1 < NCHW) { CP_WAIT(1); }      // chunk cb complete, cb+1 may fly
        else               { CP_WAIT(0); }      // FINAL chunk: full drain
        __syncthreads();               // chunk cb present (+ xs_t on cb==0)
        const float* wchunk = wt + (cb & 1) * (WCH * 256);
        #pragma unroll
        for (int kk = 0; kk < WCH; kk++) {
            float2 wv = *(const float2*)&wchunk[kk * 256 + 2 * t];
            unsigned long long w0p, w1p;
            PACK2(w0p, wv.x);
            PACK2(w1p, wv.y);
            unsigned ra = xa + (cb * WCH + kk) * 144;
            #pragma unroll
            for (int j = 0; j < 8; j++) {
                unsigned long long x01, x23;
                LDSV2(x01, x23, ra + j * 16);
                FFMA2(acc0[2 * j],     x01, w0p, acc0[2 * j]);
                FFMA2(acc0[2 * j + 1], x23, w0p, acc0[2 * j + 1]);
                FFMA2(acc1[2 * j],     x01, w1p, acc1[2 * j]);
                FFMA2(acc1[2 * j + 1], x23, w1p, acc1[2 * j + 1]);
            }
        }
        __syncthreads();               // all reads of buffer cb&1 done
        if (cb + 2 < NCHW) issue(cb + 2);
    }

    // epilogue: REDG.v2 row m cols (2t, 2t+1) into the compact destination
    float* o = dst + nblk + 2 * t;
    #pragma unroll
    for (int mp = 0; mp < 16; mp++) {
        float a0, b0, a1, b1;
        UNPACK2(a0, b0, acc0[mp]);     // col n0: rows 2mp, 2mp+1
        UNPACK2(a1, b1, acc1[mp]);     // col n1: rows 2mp, 2mp+1
        REDG2(o + (size_t)(2 * mp) * N,     a0, a1);
        REDG2(o + (size_t)(2 * mp + 1) * N, b0, b1);
    }
}

// ---------------- RoPE on summed QKV + self-cleaning zero ----------------------
__global__ __launch_bounds__(256) void k_rope2(const int* __restrict__ spp) {
    __shared__ float cs[64], sn[64];
    int tt = threadIdx.x;
    if (tt < 64) {
        int sp = *spp;
        double e    = (2.0 * (double)tt) / 128.0;
        double invf = pow(10000.0, -e);
        double ang  = (double)sp * invf;
        cs[tt] = (float)cos(ang);
        sn[tt] = (float)sin(ang);
    }
    __syncthreads();

    cudaGridDependencySynchronize();          // QKV REDG accumulation complete

    int idx = blockIdx.x * 256 + tt;

    if (idx < BATCH * 2560) {
        int m = idx / 2560;
        int p = idx % 2560;
        int h = p >> 6;                                  // head 0..39 (q then k)
        int i = p & 63;                                  // low dim
        int n  = h * 128 + i;
        int n2 = n + 64;

        float s  = g_qkv[m * QKVN + n];
        float s2 = g_qkv[m * QKVN + n2];
        g_qkv[m * QKVN + n]  = 0.f;                      // restore invariant
        g_qkv[m * QKVN + n2] = 0.f;
        float co = cs[i], si = sn[i];
        float out1 = s * co - s2 * si;
        float out2 = s2 * co + s * si;
        if (n < 4096) {
            g_q[m * DIM + n]  = out1;
            g_q[m * DIM + n2] = out2;
        } else {
            g_k[m * (NKV * HD) + (n - 4096)]  = out1;
            g_k[m * (NKV * HD) + (n2 - 4096)] = out2;
        }
    } else if (idx < BATCH * 2560 + BATCH * 1024) {
        int j = idx - BATCH * 2560;
        int m = j >> 10;
        int n = 5120 + (j & 1023);
        float s = g_qkv[m * QKVN + n];
        g_qkv[m * QKVN + n] = 0.f;                       // restore invariant
        g_v[m * (NKV * HD) + (n - 5120)] = s;
    }
}

// ---------------- flash-decode attention v5 + PDL early K streaming ------------
__global__ __launch_bounds__(128) void k_attn5(const float* __restrict__ ck,
                                               const float* __restrict__ cv,
                                               const int* __restrict__ spp) {
    extern __shared__ float sm[];
    float* qp  = sm;                  // 512 : q packed [d][4 reps]
    float* ps  = sm + 512;            // 512 : scores/probs [s][4 reps]
    float* red = sm + 1024;           // 16  : m[0..3], l[4..7]
    float* kvs = sm + 1040;           // 16896 = 128*132 (K tile, then V tile)

    const int t  = threadIdx.x;
    const int w  = t >> 5;
    const int l  = t & 31;
    const int c  = blockIdx.x;
    const int bg = blockIdx.y;
    const int sp = *spp;
    const float SCALE = 0.08838834764831845f;            // 1/sqrt(128)

    const float4* ckb = ((const float4*)ck) + (size_t)bg * CL * 32;
    const float4* cvb = ((const float4*)cv) + (size_t)bg * CL * 32;
    const float4* gk4 = ((const float4*)g_k) + bg * 32;
    const float4* gv4 = ((const float4*)g_v) + bg * 32;

    const unsigned qa   = (unsigned)__cvta_generic_to_shared(qp);
    const unsigned psa  = (unsigned)__cvta_generic_to_shared(ps);
    const unsigned kvsa = (unsigned)__cvta_generic_to_shared(kvs);

    const int s0  = c * 128;
    const int rw0 = w * 32;           // this warp's first row

    // ---- warp w issues K for its 32 rows (input reads: pre-sync, overlaps rope)
    #pragma unroll
    for (int it = 0; it < 32; it++) {
        int j   = l + 32 * it;
        int row = rw0 + (j >> 5);
        int c4  = j & 31;
        CP_ASYNC16(kvsa + row * 528 + c4 * 16,
                   (const void*)&ckb[(s0 + row) * 32 + c4]);
    }
    CP_COMMIT();

    cudaGridDependencySynchronize();          // g_q / g_k / g_v ready

    // q packed: qp[d*4 + r] (all threads)
    #pragma unroll
    for (int it = 0; it < 4; it++) {
        int idx = t + 128 * it;
        int d = idx & 127, r = idx >> 7;
        qp[d * 4 + r] = g_q[(size_t)bg * 512 + r * 128 + d];
    }
    __syncthreads();                  // qp visible (K loads still in flight)

    // ---- per-warp: wait own K, patch new-token row, score own rows ----
    CP_WAIT(0);
    __syncwarp();
    if (sp >= s0 + rw0 && sp < s0 + rw0 + 32)
        ((float4*)(kvs + (sp - s0) * 132))[l] = gk4[l];
    __syncwarp();
    {
        const int rloc = rw0 + l;
        const float4* kr = ((const float4*)kvs) + rloc * 33;
        unsigned long long a01 = 0ull, a23 = 0ull;
        #pragma unroll 8
        for (int d4 = 0; d4 < 32; d4++) {
            float4 kv = kr[d4];
            unsigned qd = qa + d4 * 64;
            unsigned long long kp, q01, q23;
            PACK2(kp, kv.x); LDSV2(q01, q23, qd +  0);
            FFMA2(a01, kp, q01, a01); FFMA2(a23, kp, q23, a23);
            PACK2(kp, kv.y); LDSV2(q01, q23, qd + 16);
            FFMA2(a01, kp, q01, a01); FFMA2(a23, kp, q23, a23);
            PACK2(kp, kv.z); LDSV2(q01, q23, qd + 32);
            FFMA2(a01, kp, q01, a01); FFMA2(a23, kp, q23, a23);
            PACK2(kp, kv.w); LDSV2(q01, q23, qd + 48);
            FFMA2(a01, kp, q01, a01); FFMA2(a23, kp, q23, a23);
        }
        float v0, v1, v2, v3;
        UNPACK2(v0, v1, a01); UNPACK2(v2, v3, a23);
        int  sg = s0 + rloc;
        bool ok = (sg <= sp);
        float4 sv;
        sv.x = ok ? v0 * SCALE : -1e9f;
        sv.y = ok ? v1 * SCALE : -1e9f;
        sv.z = ok ? v2 * SCALE : -1e9f;
        sv.w = ok ? v3 * SCALE : -1e9f;
        ((float4*)ps)[rloc] = sv;
    }

    // ---- immediately issue V for own rows (overwrites own K region) ----
    #pragma unroll
    for (int it = 0; it < 32; it++) {
        int j   = l + 32 * it;
        int row = rw0 + (j >> 5);
        int c4  = j & 31;
        CP_ASYNC16(kvsa + row * 528 + c4 * 16,
                   (const void*)&cvb[(s0 + row) * 32 + c4]);
    }
    CP_COMMIT();

    __syncthreads();                  // all scores in ps

    // ---- softmax over this chunk: warp w handles rep r = w ----
    {
        float v0 = ps[(l +  0) * 4 + w];
        float v1 = ps[(l + 32) * 4 + w];
        float v2 = ps[(l + 64) * 4 + w];
        float v3 = ps[(l + 96) * 4 + w];
        float mx = fmaxf(fmaxf(v0, v1), fmaxf(v2, v3));
        #pragma unroll
        for (int off = 16; off > 0; off >>= 1)
            mx = fmaxf(mx, __shfl_xor_sync(0xffffffffu, mx, off));
        float e0 = expf(v0 - mx), e1 = expf(v1 - mx);
        float e2 = expf(v2 - mx), e3 = expf(v3 - mx);
        float sum = e0 + e1 + e2 + e3;
        #pragma unroll
        for (int off = 16; off > 0; off >>= 1)
            sum += __shfl_xor_sync(0xffffffffu, sum, off);
        ps[(l +  0) * 4 + w] = e0;
        ps[(l + 32) * 4 + w] = e1;
        ps[(l + 64) * 4 + w] = e2;
        ps[(l + 96) * 4 + w] = e3;
        if (l == 0) { red[w] = mx; red[4 + w] = sum; }
    }

    // ---- wait own V, patch own-range new-token V row ----
    CP_WAIT(0);
    __syncwarp();
    if (sp >= s0 + rw0 && sp < s0 + rw0 + 32)
        ((float4*)(kvs + (sp - s0) * 132))[l] = gv4[l];
    __syncthreads();                  // all V rows + all probs visible

    // ---- PV: thread t owns head dim d = t, full 128 rows ----
    unsigned long long o01 = 0ull, o23 = 0ull;
    #pragma unroll 8
    for (int s = 0; s < 128; s++) {
        float vv = kvs[s * 132 + t];
        unsigned long long vp, p01, p23;
        PACK2(vp, vv);
        LDSV2(p01, p23, psa + s * 16);
        FFMA2(o01, vp, p01, o01);
        FFMA2(o23, vp, p23, o23);
    }

    float o0, o1, o2, o3;
    UNPACK2(o0, o1, o01);
    UNPACK2(o2, o3, o23);
    size_t pb = ((size_t)bg * NCH + c) * REP;
    g_pacc[(pb + 0) * HD + t] = o0;
    g_pacc[(pb + 1) * HD + t] = o1;
    g_pacc[(pb + 2) * HD + t] = o2;
    g_pacc[(pb + 3) * HD + t] = o3;
    if (t < REP) { g_pm[pb + t] = red[t]; g_pl[pb + t] = red[4 + t]; }
}

// ---------------- combine split-S partials v4 + d_out zeroing ------------------
__global__ __launch_bounds__(512) void k_combine4(float* __restrict__ out) {
    __shared__ float sm_m[NCH * REP], sm_l[NCH * REP];
    __shared__ float wgt[NCH * REP];
    __shared__ float Msh[REP], invL[REP];
    const int bg = blockIdx.x;
    const int t  = threadIdx.x;

    cudaGridDependencySynchronize();          // attention partials ready

    out[(size_t)bg * 512 + t] = 0.f;          // zero REDG accumulator for WO

    if (t < NCH * REP) {
        sm_m[t] = g_pm[bg * NCH * REP + t];
        sm_l[t] = g_pl[bg * NCH * REP + t];
    }
    __syncthreads();
    if (t < REP) {
        float M = -1e30f;
        #pragma unroll
        for (int cc = 0; cc < NCH; cc++) M = fmaxf(M, sm_m[cc * REP + t]);
        Msh[t] = M;
    }
    __syncthreads();
    if (t < NCH * REP)
        wgt[t] = expf(sm_m[t] - Msh[t & 3]);
    __syncthreads();
    if (t < REP) {
        float L = 0.f;
        #pragma unroll
        for (int cc = 0; cc < NCH; cc++) L += sm_l[cc * REP + t] * wgt[cc * REP + t];
        invL[t] = 1.f / L;
    }
    __syncthreads();

    const int r = t >> 7;
    const int d = t & 127;
    const float* pa = g_pacc + ((size_t)bg * NCH * REP + r) * HD + d;
    float val = 0.f;
    #pragma unroll
    for (int cc = 0; cc < NCH; cc++)
        val += pa[(size_t)cc * REP * HD] * wgt[cc * REP + r];
    g_attn[(size_t)bg * 512 + r * HD + d] = val * invL[r];
}

// ---------------- launch: PDL chain --------------------------------------------
template<typename K, typename... Args>
static void launch_pdl(K kern, dim3 grid, dim3 block, int smem, bool pdl,
                       Args... args) {
    cudaLaunchConfig_t cfg = {};
    cfg.gridDim = grid;
    cfg.blockDim = block;
    cfg.dynamicSmemBytes = (size_t)smem;
    cudaLaunchAttribute attr[1];
    attr[0].id = cudaLaunchAttributeProgrammaticStreamSerialization;
    attr[0].val.programmaticStreamSerializationAllowed = 1;
    if (pdl) { cfg.attrs = attr; cfg.numAttrs = 1; }
    cudaLaunchKernelEx(&cfg, kern, args...);
}

extern "C" void kernel_launch(void* const* d_in, const int* in_sizes, int n_in,
                              void* d_out, int out_size) {
    const float* x    = (const float*)d_in[0];
    const float* wqkv = (const float*)d_in[1];
    const float* wo   = (const float*)d_in[2];
    const float* ck   = (const float*)d_in[3];
    const float* cv   = (const float*)d_in[4];
    const int*   sp   = (const int*)d_in[5];
    float*       out  = (float*)d_out;

    const int ATTN_SMEM = (512 + 512 + 16 + 16896) * 4;                    // 71744 B
    const int QKV_SMEM  = ((DIM / KSPLIT_QKV) * 36 + 2 * WCH * 256) * 4;   // 34816 B
    const int WO_SMEM   = ((DIM / KSPLIT_WO) * 36 + 2 * WCH * 256) * 4;    // 25600 B
    static int attr_done = 0;
    if (!attr_done) {
        cudaFuncSetAttribute(k_attn5, cudaFuncAttributeMaxDynamicSharedMemorySize,
                             ATTN_SMEM);
        cudaFuncSetAttribute(k_gemm6<QKVN, false, DIM / KSPLIT_QKV>,
                             cudaFuncAttributeMaxDynamicSharedMemorySize, QKV_SMEM);
        cudaFuncSetAttribute(k_gemm6<DIM, true, DIM / KSPLIT_WO>,
                             cudaFuncAttributeMaxDynamicSharedMemorySize, WO_SMEM);
        attr_done = 1;
    }

    launch_pdl(k_gemm6<QKVN, false, DIM / KSPLIT_QKV>,
               dim3(QKVN / 256, KSPLIT_QKV), dim3(128), QKV_SMEM, false,
               x, wqkv, (float*)nullptr);
    launch_pdl(k_rope2,
               dim3((BATCH * 2560 + BATCH * 1024 + 255) / 256), dim3(256), 0, true,
               sp);
    launch_pdl(k_attn5,
               dim3(NCH, BATCH * NKV), dim3(128), ATTN_SMEM, true,
               ck, cv, sp);
    launch_pdl(k_combine4,
               dim3(BATCH * NKV), dim3(512), 0, true,
               out);
    launch_pdl(k_gemm6<DIM, true, DIM / KSPLIT_WO>,
               dim3(DIM / 256, KSPLIT_WO), dim3(128), WO_SMEM, true,
               (const float*)nullptr, wo, out);
}

// round 17
// speedup vs baseline: 1.0373x; 1.0373x over previous
#include <cuda_runtime.h>
#include <cuda_bf16.h>
#include <math.h>

#define BATCH   32
#define DIM     4096
#define NKV     8
#define REP     4
#define HD      128
#define QKVN    6144      // (32 + 2*8) * 128
#define CL      2176      // cache length
#define NCH     17        // 17 * 128 = 2176
#define KSPLIT_QKV  32
#define KSPLIT_WO   64

// ---------------- f32x2 packed-math helpers -----------------------------------
#define FFMA2(d, a, b, c) \
    asm("fma.rn.f32x2 %0, %1, %2, %3;" : "=l"(d) : "l"(a), "l"(b), "l"(c))
#define PACK2(d, s) \
    asm("mov.b64 %0, {%1, %1};" : "=l"(d) : "f"(s))
#define UNPACK2(lo, hi, v) \
    asm("mov.b64 {%0, %1}, %2;" : "=f"(lo), "=f"(hi) : "l"(v))
#define LDSV2(p01, p23, addr) \
    asm("ld.shared.v2.u64 {%0, %1}, [%2];" : "=l"(p01), "=l"(p23) : "r"(addr))

// vectorized no-return reduction (sm_90+): adds {a,b} to 8B-aligned global pair
#define REDG2(ptr, a, b) \
    asm volatile("red.global.add.v2.f32 [%0], {%1, %2};" \
                 :: "l"(ptr), "f"(a), "f"(b) : "memory")

// ---------------- cp.async helpers ---------------------------------------------
#define CP_ASYNC16(dst_s, src_g) \
    asm volatile("cp.async.cg.shared.global [%0], [%1], 16;" \
                 :: "r"(dst_s), "l"(src_g) : "memory")
#define CP_COMMIT() asm volatile("cp.async.commit_group;" ::: "memory")
#define CP_WAIT(n)  asm volatile("cp.async.wait_group %0;" :: "n"(n) : "memory")

// ---------------- scratch (static device globals; no allocs allowed) ----------
__device__ float g_qkv[BATCH * QKVN];                    // 0.79 MB (L2-resident)
__device__ float g_q[BATCH * DIM];                       // (b, g, r, d)
__device__ float g_k[BATCH * NKV * HD];
__device__ float g_v[BATCH * NKV * HD];
__device__ float g_pacc[(size_t)BATCH * NKV * NCH * REP * HD];
__device__ float g_pm[BATCH * NKV * NCH * REP];
__device__ float g_pl[BATCH * NKV * NCH * REP];
__device__ float g_attn[BATCH * DIM];

// ---------------- skinny GEMM v5 (R15 config): cp.async + REDG.v2 --------------
// out[32, N] accumulated over K-splits via red.global.add.v2.f32 into a compact
// L2-resident destination (g_qkv for QKV; d_out for WO). grid(N/256, NSPLIT),
// 128 threads; thread owns adjacent cols (nblk+2t, nblk+2t+1).
// Weight chunks: 16 rows x 256 cols (16 KB), double-buffered.
// Final chunk uses wait_group 0 (R8 race fix).
template<int N, bool WO, int KC>
__global__ __launch_bounds__(128) void k_gemm5(const float* __restrict__ xsrc,
                                               const float* __restrict__ w,
                                               float* __restrict__ dstout) {
    extern __shared__ float smg[];
    float* xs_t = smg;                 // KC * 36 floats
    float* wt   = smg + KC * 36;       // 2 * 16 * 256 floats

    const int t    = threadIdx.x;
    const int k0   = blockIdx.y * KC;
    const int nblk = blockIdx.x * 256;
    constexpr int NCHW = KC / 16;      // weight chunks

    const unsigned wts = (unsigned)__cvta_generic_to_shared(wt);

    // issue weight chunk cb (16 rows x 256 cols = 16 KB) into buffer cb&1
    auto issue = [&](int cb) {
        const float* src = w + (size_t)(k0 + cb * 16) * N + nblk;
        unsigned dsts = wts + (cb & 1) * 16384;
        #pragma unroll
        for (int it = 0; it < 8; it++) {
            int idx = t + 128 * it;            // 0..1023
            int row = idx >> 6;                // 64 x 16B per row
            int c16 = idx & 63;
            CP_ASYNC16(dsts + (row * 256 + c16 * 4) * 4,
                       (const void*)(src + (size_t)row * N + c16 * 4));
        }
        CP_COMMIT();
    };
    issue(0);
    issue(1);

    if (WO) cudaGridDependencySynchronize();   // g_attn + zeroed d_out ready

    const float* xbase = WO ? (const float*)g_attn : xsrc;
    float*       dst   = WO ? dstout : (float*)g_qkv;

    // load + transpose x chunk: [32][KC] -> xs_t[k][m]
    const float4* xg = (const float4*)xbase;
    #pragma unroll
    for (int j = t; j < 8 * KC; j += 128) {
        int m  = j / (KC / 4);
        int c4 = j % (KC / 4);
        float4 v = xg[m * (DIM / 4) + (k0 >> 2) + c4];
        xs_t[(4 * c4 + 0) * 36 + m] = v.x;
        xs_t[(4 * c4 + 1) * 36 + m] = v.y;
        xs_t[(4 * c4 + 2) * 36 + m] = v.z;
        xs_t[(4 * c4 + 3) * 36 + m] = v.w;
    }

    const unsigned xa = (unsigned)__cvta_generic_to_shared(xs_t);

    unsigned long long acc0[16], acc1[16];
    #pragma unroll
    for (int mp = 0; mp < 16; mp++) { acc0[mp] = 0ull; acc1[mp] = 0ull; }

    for (int cb = 0; cb < NCHW; cb++) {
        if (cb + 1 < NCHW) { CP_WAIT(1); }      // chunk cb complete, cb+1 may fly
        else               { CP_WAIT(0); }      // FINAL chunk: full drain
        __syncthreads();               // chunk cb present (+ xs_t on cb==0)
        const float* wchunk = wt + (cb & 1) * 4096;
        #pragma unroll
        for (int kk = 0; kk < 16; kk++) {
            float2 wv = *(const float2*)&wchunk[kk * 256 + 2 * t];
            unsigned long long w0p, w1p;
            PACK2(w0p, wv.x);
            PACK2(w1p, wv.y);
            unsigned ra = xa + (cb * 16 + kk) * 144;
            #pragma unroll
            for (int j = 0; j < 8; j++) {
                unsigned long long x01, x23;
                LDSV2(x01, x23, ra + j * 16);
                FFMA2(acc0[2 * j],     x01, w0p, acc0[2 * j]);
                FFMA2(acc0[2 * j + 1], x23, w0p, acc0[2 * j + 1]);
                FFMA2(acc1[2 * j],     x01, w1p, acc1[2 * j]);
                FFMA2(acc1[2 * j + 1], x23, w1p, acc1[2 * j + 1]);
            }
        }
        __syncthreads();               // all reads of buffer cb&1 done
        if (cb + 2 < NCHW) issue(cb + 2);
    }

    // epilogue: REDG.v2 row m cols (2t, 2t+1) into the compact destination
    float* o = dst + nblk + 2 * t;
    #pragma unroll
    for (int mp = 0; mp < 16; mp++) {
        float a0, b0, a1, b1;
        UNPACK2(a0, b0, acc0[mp]);     // col n0: rows 2mp, 2mp+1
        UNPACK2(a1, b1, acc1[mp]);     // col n1: rows 2mp, 2mp+1
        REDG2(o + (size_t)(2 * mp) * N,     a0, a1);
        REDG2(o + (size_t)(2 * mp + 1) * N, b0, b1);
    }
}

// ---------------- RoPE on summed QKV + self-cleaning zero ----------------------
__global__ __launch_bounds__(256) void k_rope2(const int* __restrict__ spp) {
    __shared__ float cs[64], sn[64];
    int tt = threadIdx.x;
    if (tt < 64) {
        int sp = *spp;
        double e    = (2.0 * (double)tt) / 128.0;
        double invf = pow(10000.0, -e);
        double ang  = (double)sp * invf;
        cs[tt] = (float)cos(ang);
        sn[tt] = (float)sin(ang);
    }
    __syncthreads();

    cudaGridDependencySynchronize();          // QKV REDG accumulation complete

    int idx = blockIdx.x * 256 + tt;

    if (idx < BATCH * 2560) {
        int m = idx / 2560;
        int p = idx % 2560;
        int h = p >> 6;                                  // head 0..39 (q then k)
        int i = p & 63;                                  // low dim
        int n  = h * 128 + i;
        int n2 = n + 64;

        float s  = g_qkv[m * QKVN + n];
        float s2 = g_qkv[m * QKVN + n2];
        g_qkv[m * QKVN + n]  = 0.f;                      // restore invariant
        g_qkv[m * QKVN + n2] = 0.f;
        float co = cs[i], si = sn[i];
        float out1 = s * co - s2 * si;
        float out2 = s2 * co + s * si;
        if (n < 4096) {
            g_q[m * DIM + n]  = out1;
            g_q[m * DIM + n2] = out2;
        } else {
            g_k[m * (NKV * HD) + (n - 4096)]  = out1;
            g_k[m * (NKV * HD) + (n2 - 4096)] = out2;
        }
    } else if (idx < BATCH * 2560 + BATCH * 1024) {
        int j = idx - BATCH * 2560;
        int m = j >> 10;
        int n = 5120 + (j & 1023);
        float s = g_qkv[m * QKVN + n];
        g_qkv[m * QKVN + n] = 0.f;                       // restore invariant
        g_v[m * (NKV * HD) + (n - 5120)] = s;
    }
}

// ---------------- flash-decode attention v6: masked-chunk early exit -----------
// Blocks whose entire chunk is masked (s0 > sp) write zero partials and exit
// BEFORE issuing any cache traffic: for sp=2047 this skips chunk 16 entirely
// (1/17 of K+V streaming). Contribution is identically zero either way
// (combine weight exp(m - M) = 0 exactly), so output is bitwise unchanged.
__global__ __launch_bounds__(128) void k_attn6(const float* __restrict__ ck,
                                               const float* __restrict__ cv,
                                               const int* __restrict__ spp) {
    extern __shared__ float sm[];
    float* qp  = sm;                  // 512 : q packed [d][4 reps]
    float* ps  = sm + 512;            // 512 : scores/probs [s][4 reps]
    float* red = sm + 1024;           // 16  : m[0..3], l[4..7]
    float* kvs = sm + 1040;           // 16896 = 128*132 (K tile, then V tile)

    const int t  = threadIdx.x;
    const int w  = t >> 5;
    const int l  = t & 31;
    const int c  = blockIdx.x;
    const int bg = blockIdx.y;
    const int sp = *spp;
    const float SCALE = 0.08838834764831845f;            // 1/sqrt(128)

    const int s0  = c * 128;

    // ---- fully-masked chunk: zero partials, exit (no cache traffic) ----
    if (s0 > sp) {
        size_t pb = ((size_t)bg * NCH + c) * REP;
        #pragma unroll
        for (int r = 0; r < REP; r++) g_pacc[(pb + r) * HD + t] = 0.f;
        if (t < REP) { g_pm[pb + t] = -1e30f; g_pl[pb + t] = 0.f; }
        return;
    }

    const float4* ckb = ((const float4*)ck) + (size_t)bg * CL * 32;
    const float4* cvb = ((const float4*)cv) + (size_t)bg * CL * 32;
    const float4* gk4 = ((const float4*)g_k) + bg * 32;
    const float4* gv4 = ((const float4*)g_v) + bg * 32;

    const unsigned qa   = (unsigned)__cvta_generic_to_shared(qp);
    const unsigned psa  = (unsigned)__cvta_generic_to_shared(ps);
    const unsigned kvsa = (unsigned)__cvta_generic_to_shared(kvs);

    const int rw0 = w * 32;           // this warp's first row

    // ---- warp w issues K for its 32 rows (input reads: pre-sync, overlaps rope)
    #pragma unroll
    for (int it = 0; it < 32; it++) {
        int j   = l + 32 * it;
        int row = rw0 + (j >> 5);
        int c4  = j & 31;
        CP_ASYNC16(kvsa + row * 528 + c4 * 16,
                   (const void*)&ckb[(s0 + row) * 32 + c4]);
    }
    CP_COMMIT();

    cudaGridDependencySynchronize();          // g_q / g_k / g_v ready

    // q packed: qp[d*4 + r] (all threads)
    #pragma unroll
    for (int it = 0; it < 4; it++) {
        int idx = t + 128 * it;
        int d = idx & 127, r = idx >> 7;
        qp[d * 4 + r] = g_q[(size_t)bg * 512 + r * 128 + d];
    }
    __syncthreads();                  // qp visible (K loads still in flight)

    // ---- per-warp: wait own K, patch new-token row, score own rows ----
    CP_WAIT(0);
    __syncwarp();
    if (sp >= s0 + rw0 && sp < s0 + rw0 + 32)
        ((float4*)(kvs + (sp - s0) * 132))[l] = gk4[l];
    __syncwarp();
    {
        const int rloc = rw0 + l;
        const float4* kr = ((const float4*)kvs) + rloc * 33;
        unsigned long long a01 = 0ull, a23 = 0ull;
        #pragma unroll 8
        for (int d4 = 0; d4 < 32; d4++) {
            float4 kv = kr[d4];
            unsigned qd = qa + d4 * 64;
            unsigned long long kp, q01, q23;
            PACK2(kp, kv.x); LDSV2(q01, q23, qd +  0);
            FFMA2(a01, kp, q01, a01); FFMA2(a23, kp, q23, a23);
            PACK2(kp, kv.y); LDSV2(q01, q23, qd + 16);
            FFMA2(a01, kp, q01, a01); FFMA2(a23, kp, q23, a23);
            PACK2(kp, kv.z); LDSV2(q01, q23, qd + 32);
            FFMA2(a01, kp, q01, a01); FFMA2(a23, kp, q23, a23);
            PACK2(kp, kv.w); LDSV2(q01, q23, qd + 48);
            FFMA2(a01, kp, q01, a01); FFMA2(a23, kp, q23, a23);
        }
        float v0, v1, v2, v3;
        UNPACK2(v0, v1, a01); UNPACK2(v2, v3, a23);
        int  sg = s0 + rloc;
        bool ok = (sg <= sp);
        float4 sv;
        sv.x = ok ? v0 * SCALE : -1e9f;
        sv.y = ok ? v1 * SCALE : -1e9f;
        sv.z = ok ? v2 * SCALE : -1e9f;
        sv.w = ok ? v3 * SCALE : -1e9f;
        ((float4*)ps)[rloc] = sv;
    }

    // ---- immediately issue V for own rows (overwrites own K region) ----
    #pragma unroll
    for (int it = 0; it < 32; it++) {
        int j   = l + 32 * it;
        int row = rw0 + (j >> 5);
        int c4  = j & 31;
        CP_ASYNC16(kvsa + row * 528 + c4 * 16,
                   (const void*)&cvb[(s0 + row) * 32 + c4]);
    }
    CP_COMMIT();

    __syncthreads();                  // all scores in ps

    // ---- softmax over this chunk: warp w handles rep r = w ----
    {
        float v0 = ps[(l +  0) * 4 + w];
        float v1 = ps[(l + 32) * 4 + w];
        float v2 = ps[(l + 64) * 4 + w];
        float v3 = ps[(l + 96) * 4 + w];
        float mx = fmaxf(fmaxf(v0, v1), fmaxf(v2, v3));
        #pragma unroll
        for (int off = 16; off > 0; off >>= 1)
            mx = fmaxf(mx, __shfl_xor_sync(0xffffffffu, mx, off));
        float e0 = expf(v0 - mx), e1 = expf(v1 - mx);
        float e2 = expf(v2 - mx), e3 = expf(v3 - mx);
        float sum = e0 + e1 + e2 + e3;
        #pragma unroll
        for (int off = 16; off > 0; off >>= 1)
            sum += __shfl_xor_sync(0xffffffffu, sum, off);
        ps[(l +  0) * 4 + w] = e0;
        ps[(l + 32) * 4 + w] = e1;
        ps[(l + 64) * 4 + w] = e2;
        ps[(l + 96) * 4 + w] = e3;
        if (l == 0) { red[w] = mx; red[4 + w] = sum; }
    }

    // ---- wait own V, patch own-range new-token V row ----
    CP_WAIT(0);
    __syncwarp();
    if (sp >= s0 + rw0 && sp < s0 + rw0 + 32)
        ((float4*)(kvs + (sp - s0) * 132))[l] = gv4[l];
    __syncthreads();                  // all V rows + all probs visible

    // ---- PV: thread t owns head dim d = t, full 128 rows ----
    unsigned long long o01 = 0ull, o23 = 0ull;
    #pragma unroll 8
    for (int s = 0; s < 128; s++) {
        float vv = kvs[s * 132 + t];
        unsigned long long vp, p01, p23;
        PACK2(vp, vv);
        LDSV2(p01, p23, psa + s * 16);
        FFMA2(o01, vp, p01, o01);
        FFMA2(o23, vp, p23, o23);
    }

    float o0, o1, o2, o3;
    UNPACK2(o0, o1, o01);
    UNPACK2(o2, o3, o23);
    size_t pb = ((size_t)bg * NCH + c) * REP;
    g_pacc[(pb + 0) * HD + t] = o0;
    g_pacc[(pb + 1) * HD + t] = o1;
    g_pacc[(pb + 2) * HD + t] = o2;
    g_pacc[(pb + 3) * HD + t] = o3;
    if (t < REP) { g_pm[pb + t] = red[t]; g_pl[pb + t] = red[4 + t]; }
}

// ---------------- combine split-S partials v4 + d_out zeroing ------------------
__global__ __launch_bounds__(512) void k_combine4(float* __restrict__ out) {
    __shared__ float sm_m[NCH * REP], sm_l[NCH * REP];
    __shared__ float wgt[NCH * REP];
    __shared__ float Msh[REP], invL[REP];
    const int bg = blockIdx.x;
    const int t  = threadIdx.x;

    cudaGridDependencySynchronize();          // attention partials ready

    out[(size_t)bg * 512 + t] = 0.f;          // zero REDG accumulator for WO

    if (t < NCH * REP) {
        sm_m[t] = g_pm[bg * NCH * REP + t];
        sm_l[t] = g_pl[bg * NCH * REP + t];
    }
    __syncthreads();
    if (t < REP) {
        float M = -1e30f;
        #pragma unroll
        for (int cc = 0; cc < NCH; cc++) M = fmaxf(M, sm_m[cc * REP + t]);
        Msh[t] = M;
    }
    __syncthreads();
    if (t < NCH * REP)
        wgt[t] = expf(sm_m[t] - Msh[t & 3]);
    __syncthreads();
    if (t < REP) {
        float L = 0.f;
        #pragma unroll
        for (int cc = 0; cc < NCH; cc++) L += sm_l[cc * REP + t] * wgt[cc * REP + t];
        invL[t] = 1.f / L;
    }
    __syncthreads();

    const int r = t >> 7;
    const int d = t & 127;
    const float* pa = g_pacc + ((size_t)bg * NCH * REP + r) * HD + d;
    float val = 0.f;
    #pragma unroll
    for (int cc = 0; cc < NCH; cc++)
        val += pa[(size_t)cc * REP * HD] * wgt[cc * REP + r];
    g_attn[(size_t)bg * 512 + r * HD + d] = val * invL[r];
}

// ---------------- launch: PDL chain --------------------------------------------
template<typename K, typename... Args>
static void launch_pdl(K kern, dim3 grid, dim3 block, int smem, bool pdl,
                       Args... args) {
    cudaLaunchConfig_t cfg = {};
    cfg.gridDim = grid;
    cfg.blockDim = block;
    cfg.dynamicSmemBytes = (size_t)smem;
    cudaLaunchAttribute attr[1];
    attr[0].id = cudaLaunchAttributeProgrammaticStreamSerialization;
    attr[0].val.programmaticStreamSerializationAllowed = 1;
    if (pdl) { cfg.attrs = attr; cfg.numAttrs = 1; }
    cudaLaunchKernelEx(&cfg, kern, args...);
}

extern "C" void kernel_launch(void* const* d_in, const int* in_sizes, int n_in,
                              void* d_out, int out_size) {
    const float* x    = (const float*)d_in[0];
    const float* wqkv = (const float*)d_in[1];
    const float* wo   = (const float*)d_in[2];
    const float* ck   = (const float*)d_in[3];
    const float* cv   = (const float*)d_in[4];
    const int*   sp   = (const int*)d_in[5];
    float*       out  = (float*)d_out;

    const int ATTN_SMEM = (512 + 512 + 16 + 16896) * 4;            // 71744 B
    const int QKV_SMEM  = ((DIM / KSPLIT_QKV) * 36 + 8192) * 4;    // 51200 B
    const int WO_SMEM   = ((DIM / KSPLIT_WO) * 36 + 8192) * 4;     // 41984 B
    static int attr_done = 0;
    if (!attr_done) {
        cudaFuncSetAttribute(k_attn6, cudaFuncAttributeMaxDynamicSharedMemorySize,
                             ATTN_SMEM);
        cudaFuncSetAttribute(k_gemm5<QKVN, false, DIM / KSPLIT_QKV>,
                             cudaFuncAttributeMaxDynamicSharedMemorySize, QKV_SMEM);
        cudaFuncSetAttribute(k_gemm5<DIM, true, DIM / KSPLIT_WO>,
                             cudaFuncAttributeMaxDynamicSharedMemorySize, WO_SMEM);
        attr_done = 1;
    }

    launch_pdl(k_gemm5<QKVN, false, DIM / KSPLIT_QKV>,
               dim3(QKVN / 256, KSPLIT_QKV), dim3(128), QKV_SMEM, false,
               x, wqkv, (float*)nullptr);
    launch_pdl(k_rope2,
               dim3((BATCH * 2560 + BATCH * 1024 + 255) / 256), dim3(256), 0, true,
               sp);
    launch_pdl(k_attn6,
               dim3(NCH, BATCH * NKV), dim3(128), ATTN_SMEM, true,
               ck, cv, sp);
    launch_pdl(k_combine4,
               dim3(BATCH * NKV), dim3(512), 0, true,
               out);
    launch_pdl(k_gemm5<DIM, true, DIM / KSPLIT_WO>,
               dim3(DIM / 256, KSPLIT_WO), dim3(128), WO_SMEM, true,
               (const float*)nullptr, wo, out);
}